// round 15
// baseline (speedup 1.0000x reference)
#include <cuda_runtime.h>
#include <cuda_bf16.h>
#include <math.h>
#include <stdint.h>
#include <cstdint>

#define B_    16
#define T_    8192
#define F_    256
#define NL_   3
#define KS_   3
#define NB_   10
#define PROJ_ 29
#define BT_   (B_*T_)
#define TBND  5.0f

__device__ float g_h[(size_t)BT_ * F_];     // residual ping
__device__ float g_h2[(size_t)BT_ * F_];    // residual pong
__device__ float g_lad[BT_];
__device__ uint4 g_Bfrag[NL_ * 32 * 16 * 32];
__device__ uint4 g_Pfrag[4 * 16 * 32];

__device__ __forceinline__ float gelu_f(float v) {
    return 0.5f * v * (1.0f + erff(v * 0.7071067811865476f));
}

__device__ __forceinline__ float softplus_f(float v) {
    return fmaxf(v, 0.f) + log1pf(expf(-fabsf(v)));
}

__device__ __forceinline__ void mma16816(float* d, const uint32_t* a,
                                         uint32_t b0, uint32_t b1) {
    asm volatile(
        "mma.sync.aligned.m16n8k16.row.col.f32.bf16.bf16.f32 "
        "{%0,%1,%2,%3}, {%4,%5,%6,%7}, {%8,%9}, {%0,%1,%2,%3};"
        : "+f"(d[0]), "+f"(d[1]), "+f"(d[2]), "+f"(d[3])
        : "r"(a[0]), "r"(a[1]), "r"(a[2]), "r"(a[3]), "r"(b0), "r"(b1));
}

__device__ __forceinline__ void ldmx4(uint32_t* r, uint32_t addr) {
    asm volatile("ldmatrix.sync.aligned.m8n8.x4.shared.b16 {%0,%1,%2,%3}, [%4];"
        : "=r"(r[0]), "=r"(r[1]), "=r"(r[2]), "=r"(r[3]) : "r"(addr));
}

__device__ __forceinline__ uint32_t pack_bf16x2(float x, float y) {
    __nv_bfloat162 p = __halves2bfloat162(__float2bfloat16(x), __float2bfloat16(y));
    return *reinterpret_cast<uint32_t*>(&p);
}

#define GROUP_BAR(g) \
    asm volatile("bar.sync %0, 256;" :: "r"(1 + (g)) : "memory")

// ---------------------------------------------------------------------------
// Kernel 0a: pack w11 into mma B fragments (hi/lo split)
// ---------------------------------------------------------------------------
__global__ void prep_bfrag_kernel(const float* __restrict__ w11) {
    int blk  = blockIdx.x;
    int lane = threadIdx.x;
    int ks   = blk & 15;
    int nt   = (blk >> 4) & 31;
    int l    = blk >> 9;
    int tg   = lane >> 2, tid = lane & 3;
    int n    = nt * 8 + tg;
    int k0   = ks * 16 + tid * 2;

    const float* w = w11 + (size_t)l * F_ * F_;
    float v00 = w[(size_t)(k0    ) * F_ + n];
    float v01 = w[(size_t)(k0 + 1) * F_ + n];
    float v10 = w[(size_t)(k0 + 8) * F_ + n];
    float v11 = w[(size_t)(k0 + 9) * F_ + n];

    float h00 = __bfloat162float(__float2bfloat16(v00));
    float h01 = __bfloat162float(__float2bfloat16(v01));
    float h10 = __bfloat162float(__float2bfloat16(v10));
    float h11 = __bfloat162float(__float2bfloat16(v11));

    uint4 o;
    o.x = pack_bf16x2(v00, v01);
    o.y = pack_bf16x2(v10, v11);
    o.z = pack_bf16x2(v00 - h00, v01 - h01);
    o.w = pack_bf16x2(v10 - h10, v11 - h11);
    g_Bfrag[(size_t)blk * 32 + lane] = o;
}

// ---------------------------------------------------------------------------
// Kernel 0b: pack w_proj [256,29] into fragments, N padded to 32
// ---------------------------------------------------------------------------
__global__ void prep_pfrag_kernel(const float* __restrict__ w_proj) {
    int blk  = blockIdx.x;
    int lane = threadIdx.x;
    int ks   = blk & 15;
    int nt   = blk >> 4;
    int tg   = lane >> 2, tid = lane & 3;
    int n    = nt * 8 + tg;
    int k0   = ks * 16 + tid * 2;

    float v00 = (n < PROJ_) ? w_proj[(size_t)(k0    ) * PROJ_ + n] : 0.f;
    float v01 = (n < PROJ_) ? w_proj[(size_t)(k0 + 1) * PROJ_ + n] : 0.f;
    float v10 = (n < PROJ_) ? w_proj[(size_t)(k0 + 8) * PROJ_ + n] : 0.f;
    float v11 = (n < PROJ_) ? w_proj[(size_t)(k0 + 9) * PROJ_ + n] : 0.f;

    float h00 = __bfloat162float(__float2bfloat16(v00));
    float h01 = __bfloat162float(__float2bfloat16(v01));
    float h10 = __bfloat162float(__float2bfloat16(v10));
    float h11 = __bfloat162float(__float2bfloat16(v11));

    uint4 o;
    o.x = pack_bf16x2(v00, v01);
    o.y = pack_bf16x2(v10, v11);
    o.z = pack_bf16x2(v00 - h00, v01 - h01);
    o.w = pack_bf16x2(v10 - h10, v11 - h11);
    g_Pfrag[(size_t)blk * 32 + lane] = o;
}

// ---------------------------------------------------------------------------
// Kernel 1: FUSED layer (M=64, 512 threads, 2 CTAs/SM).
// Phases 1-3 synchronized per M-group via named barriers (2 indep groups/CTA).
// layer==2 additionally runs phase 4: proj mini-GEMM + RQ spline.
// ---------------------------------------------------------------------------
#define AROW    264
#define GSMEM   (2 * 64 * AROW * 2 + 256)

// group-disjoint stag placement inside the A region:
// group g owns Ahi rows 32g..32g+31 (byte 16896*g) and Alo rows (33792+16896*g)
// stag row r (0..63): g=r>>5, half=(r&31)>>4, idx=r&15 -> 1040B rows
__device__ __forceinline__ float* stag_row(char* base, int r) {
    int g = r >> 5, lr = r & 31;
    int half = lr >> 4, idx = lr & 15;
    return reinterpret_cast<float*>(base + g * 16896 + half * 33792 + idx * 1040);
}

__global__ void __launch_bounds__(512, 2)
layer_fused_kernel(int layer, int dil,
                   const float* __restrict__ x,
                   const float* __restrict__ mask,
                   const float* __restrict__ w_pre,
                   const float* __restrict__ b_pre,
                   const float* __restrict__ dwk,
                   const float* __restrict__ dwb,
                   const float* __restrict__ g1,
                   const float* __restrict__ b1,
                   const float* __restrict__ b11,
                   const float* __restrict__ g2,
                   const float* __restrict__ b2,
                   const float* __restrict__ b_proj,
                   float* __restrict__ out) {
    extern __shared__ char dyn[];
    __shared__ float4 s_k[3][64], s_b[64], s_g[64], s_bb[64], s_wp[64], s_bp[64];
    __shared__ float pstag[64][34];

    char* basep = (char*)(((uintptr_t)dyn + 15) & ~(uintptr_t)15);
    __nv_bfloat16* Ahi = reinterpret_cast<__nv_bfloat16*>(basep);
    __nv_bfloat16* Alo = Ahi + 64 * AROW;

    const int tid  = threadIdx.x;
    const int wid  = tid >> 5;
    const int lane = tid & 31;
    const int tg   = lane >> 2, tq = lane & 3;
    const int wm   = wid >> 3;
    const int wn   = wid & 7;
    const int m0   = blockIdx.x * 64;

    const float* h_in  = (layer == 1) ? g_h : g_h2;
    float*       h_out = (layer == 1) ? g_h2 : g_h;

    // ---- stage params (full sync once) ----
    if (tid < 64) {
        s_k[0][tid] = reinterpret_cast<const float4*>(dwk)[tid];
        s_k[1][tid] = reinterpret_cast<const float4*>(dwk)[64 + tid];
        s_k[2][tid] = reinterpret_cast<const float4*>(dwk)[128 + tid];
        s_wp[tid]   = reinterpret_cast<const float4*>(w_pre)[tid];
    } else if (tid < 128) {
        s_b[tid - 64]  = reinterpret_cast<const float4*>(dwb)[tid - 64];
        s_bp[tid - 64] = reinterpret_cast<const float4*>(b_pre)[tid - 64];
    } else if (tid < 192) {
        s_g[tid - 128] = reinterpret_cast<const float4*>(g1)[tid - 128];
    } else if (tid < 256) {
        s_bb[tid - 192] = reinterpret_cast<const float4*>(b1)[tid - 192];
    }
    __syncthreads();

    // ---- Phase 1: conv + LN1 + gelu -> A SMEM (bf16 hi/lo); 4 rows/warp ----
    #pragma unroll 1
    for (int i = 0; i < 4; i++) {
        int r   = wid * 4 + i;
        int tok = m0 + r;
        int t   = tok & (T_ - 1);

        float a[8];
        {
            float4 b0 = s_b[lane], b1v = s_b[lane + 32];
            a[0]=b0.x; a[1]=b0.y; a[2]=b0.z; a[3]=b0.w;
            a[4]=b1v.x; a[5]=b1v.y; a[6]=b1v.z; a[7]=b1v.w;
        }

        #pragma unroll
        for (int tap = 0; tap < 3; tap++) {
            int off = (tap - 1) * dil;
            int tt  = t + off;
            if (tt >= 0 && tt < T_) {
                float mm = __ldg(&mask[tok + off]);
                float4 k0 = s_k[tap][lane], k1 = s_k[tap][lane + 32];
                float karr[8] = {k0.x,k0.y,k0.z,k0.w,k1.x,k1.y,k1.z,k1.w};
                if (layer == 0) {
                    float x0 = __ldg(&x[(size_t)(tok + off) * 2]);
                    float4 w0 = s_wp[lane], w1 = s_wp[lane + 32];
                    float4 p0 = s_bp[lane], p1 = s_bp[lane + 32];
                    float wpar[8] = {w0.x,w0.y,w0.z,w0.w,w1.x,w1.y,w1.z,w1.w};
                    float bpar[8] = {p0.x,p0.y,p0.z,p0.w,p1.x,p1.y,p1.z,p1.w};
                    float xm = x0 * mm;
                    #pragma unroll
                    for (int j = 0; j < 8; j++)
                        a[j] += (xm * wpar[j] + mm * bpar[j]) * karr[j];
                } else {
                    const float4* hr = reinterpret_cast<const float4*>(
                        h_in + (size_t)(tok + off) * F_);
                    float4 h0 = hr[lane], h1 = hr[lane + 32];
                    a[0] += h0.x * mm * karr[0]; a[1] += h0.y * mm * karr[1];
                    a[2] += h0.z * mm * karr[2]; a[3] += h0.w * mm * karr[3];
                    a[4] += h1.x * mm * karr[4]; a[5] += h1.y * mm * karr[5];
                    a[6] += h1.z * mm * karr[6]; a[7] += h1.w * mm * karr[7];
                }
            }
        }

        float s = 0.f, ss = 0.f;
        #pragma unroll
        for (int j = 0; j < 8; j++) { s += a[j]; ss += a[j] * a[j]; }
        #pragma unroll
        for (int o = 16; o; o >>= 1) {
            s  += __shfl_xor_sync(0xFFFFFFFFu, s,  o);
            ss += __shfl_xor_sync(0xFFFFFFFFu, ss, o);
        }
        float mean = s * (1.0f / F_);
        float rstd = rsqrtf(ss * (1.0f / F_) - mean * mean + 1e-5f);

        float4 gg0 = s_g[lane], gg1 = s_g[lane + 32];
        float4 bb0 = s_bb[lane], bb1 = s_bb[lane + 32];
        float garr[8] = {gg0.x,gg0.y,gg0.z,gg0.w,gg1.x,gg1.y,gg1.z,gg1.w};
        float barr[8] = {bb0.x,bb0.y,bb0.z,bb0.w,bb1.x,bb1.y,bb1.z,bb1.w};

        float rv[8];
        #pragma unroll
        for (int j = 0; j < 8; j++) {
            float v = (a[j] - mean) * rstd * garr[j] + barr[j];
            rv[j] = gelu_f(v);
        }
        uint2 hp0, lp0, hp1, lp1;
        float h0 = __bfloat162float(__float2bfloat16(rv[0]));
        float h1v = __bfloat162float(__float2bfloat16(rv[1]));
        float h2 = __bfloat162float(__float2bfloat16(rv[2]));
        float h3 = __bfloat162float(__float2bfloat16(rv[3]));
        float h4 = __bfloat162float(__float2bfloat16(rv[4]));
        float h5 = __bfloat162float(__float2bfloat16(rv[5]));
        float h6 = __bfloat162float(__float2bfloat16(rv[6]));
        float h7 = __bfloat162float(__float2bfloat16(rv[7]));
        hp0.x = pack_bf16x2(rv[0], rv[1]);  hp0.y = pack_bf16x2(rv[2], rv[3]);
        lp0.x = pack_bf16x2(rv[0]-h0, rv[1]-h1v); lp0.y = pack_bf16x2(rv[2]-h2, rv[3]-h3);
        hp1.x = pack_bf16x2(rv[4], rv[5]);  hp1.y = pack_bf16x2(rv[6], rv[7]);
        lp1.x = pack_bf16x2(rv[4]-h4, rv[5]-h5); lp1.y = pack_bf16x2(rv[6]-h6, rv[7]-h7);
        *reinterpret_cast<uint2*>(Ahi + r * AROW + 4*lane)       = hp0;
        *reinterpret_cast<uint2*>(Alo + r * AROW + 4*lane)       = lp0;
        *reinterpret_cast<uint2*>(Ahi + r * AROW + 128 + 4*lane) = hp1;
        *reinterpret_cast<uint2*>(Alo + r * AROW + 128 + 4*lane) = lp1;
    }
    GROUP_BAR(wm);

    // ---- Phase 2: mainloop (single-buffered B via __ldg, term-major) ----
    float d[2][4][4];
    #pragma unroll
    for (int mt = 0; mt < 2; mt++)
        #pragma unroll
        for (int nt = 0; nt < 4; nt++)
            #pragma unroll
            for (int q = 0; q < 4; q++) d[mt][nt][q] = 0.f;

    const uint4* Bbase = g_Bfrag + ((size_t)(layer * 32 + wn * 4) * 16) * 32 + lane;

    uint32_t a_hi_addr[2], a_lo_addr[2];
    {
        int r = lane & 15;
        int cb = (lane >> 4) * 16;
        #pragma unroll
        for (int mt = 0; mt < 2; mt++) {
            int row = wm * 32 + mt * 16 + r;
            a_hi_addr[mt] = (uint32_t)__cvta_generic_to_shared(Ahi + row * AROW) + cb;
            a_lo_addr[mt] = (uint32_t)__cvta_generic_to_shared(Alo + row * AROW) + cb;
        }
    }

    #pragma unroll 1
    for (int ks = 0; ks < 16; ks++) {
        uint4 bcur[4];
        #pragma unroll
        for (int nt = 0; nt < 4; nt++)
            bcur[nt] = __ldg(&Bbase[(nt * 16 + ks) * 32]);
        const uint32_t koff = ks * 32;
        #pragma unroll
        for (int mt = 0; mt < 2; mt++) {
            uint32_t ah[4], al[4];
            ldmx4(ah, a_hi_addr[mt] + koff);
            ldmx4(al, a_lo_addr[mt] + koff);
            #pragma unroll
            for (int nt = 0; nt < 4; nt++)
                mma16816(d[mt][nt], ah, bcur[nt].x, bcur[nt].y);
            #pragma unroll
            for (int nt = 0; nt < 4; nt++)
                mma16816(d[mt][nt], ah, bcur[nt].z, bcur[nt].w);
            #pragma unroll
            for (int nt = 0; nt < 4; nt++)
                mma16816(d[mt][nt], al, bcur[nt].x, bcur[nt].y);
        }
    }

    // ---- stage accum (group-local stag region) ----
    GROUP_BAR(wm);
    #pragma unroll
    for (int mt = 0; mt < 2; mt++) {
        int r0 = wm * 32 + mt * 16 + tg;
        #pragma unroll
        for (int nt = 0; nt < 4; nt++) {
            int col = wn * 32 + nt * 8 + tq * 2;
            *reinterpret_cast<float2*>(&stag_row(basep, r0)[col]) =
                make_float2(d[mt][nt][0], d[mt][nt][1]);
            *reinterpret_cast<float2*>(&stag_row(basep, r0 + 8)[col]) =
                make_float2(d[mt][nt][2], d[mt][nt][3]);
        }
    }
    GROUP_BAR(wm);

    // ---- Phase 3: LN2 + gelu + residual -> h_out; 4 rows/warp ----
    #pragma unroll 1
    for (int i = 0; i < 4; i++) {
        int row = wid * 4 + i;
        const float* srow = stag_row(basep, row);
        float4 f0 = *reinterpret_cast<const float4*>(&srow[lane * 8]);
        float4 f1 = *reinterpret_cast<const float4*>(&srow[lane * 8 + 4]);
        float4 bb0 = reinterpret_cast<const float4*>(b11)[lane * 2];
        float4 bb1 = reinterpret_cast<const float4*>(b11)[lane * 2 + 1];
        float v[8] = {f0.x + bb0.x, f0.y + bb0.y, f0.z + bb0.z, f0.w + bb0.w,
                      f1.x + bb1.x, f1.y + bb1.y, f1.z + bb1.z, f1.w + bb1.w};
        float s = 0.f, ss = 0.f;
        #pragma unroll
        for (int j = 0; j < 8; j++) { s += v[j]; ss += v[j] * v[j]; }
        #pragma unroll
        for (int o = 16; o; o >>= 1) {
            s  += __shfl_xor_sync(0xFFFFFFFFu, s,  o);
            ss += __shfl_xor_sync(0xFFFFFFFFu, ss, o);
        }
        float mean = s * (1.0f / F_);
        float rstd = rsqrtf(ss * (1.0f / F_) - mean * mean + 1e-5f);

        float4 gg0 = reinterpret_cast<const float4*>(g2)[lane * 2];
        float4 gg1 = reinterpret_cast<const float4*>(g2)[lane * 2 + 1];
        float4 zb0 = reinterpret_cast<const float4*>(b2)[lane * 2];
        float4 zb1 = reinterpret_cast<const float4*>(b2)[lane * 2 + 1];
        float garr[8] = {gg0.x,gg0.y,gg0.z,gg0.w,gg1.x,gg1.y,gg1.z,gg1.w};
        float barr[8] = {zb0.x,zb0.y,zb0.z,zb0.w,zb1.x,zb1.y,zb1.z,zb1.w};

        float hv[8];
        if (layer == 0) {
            float x0 = __ldg(&x[(size_t)(m0 + row) * 2]);
            float4 w0 = s_wp[lane * 2], w1 = s_wp[lane * 2 + 1];
            float4 p0 = s_bp[lane * 2], p1 = s_bp[lane * 2 + 1];
            hv[0] = x0*w0.x + p0.x; hv[1] = x0*w0.y + p0.y;
            hv[2] = x0*w0.z + p0.z; hv[3] = x0*w0.w + p0.w;
            hv[4] = x0*w1.x + p1.x; hv[5] = x0*w1.y + p1.y;
            hv[6] = x0*w1.z + p1.z; hv[7] = x0*w1.w + p1.w;
        } else {
            const float4* hp = reinterpret_cast<const float4*>(
                h_in + (size_t)(m0 + row) * F_ + lane * 8);
            float4 h0 = hp[0], h1 = hp[1];
            hv[0]=h0.x; hv[1]=h0.y; hv[2]=h0.z; hv[3]=h0.w;
            hv[4]=h1.x; hv[5]=h1.y; hv[6]=h1.z; hv[7]=h1.w;
        }
        #pragma unroll
        for (int j = 0; j < 8; j++) {
            float z = (v[j] - mean) * rstd * garr[j] + barr[j];
            hv[j] += gelu_f(z);
        }
        float4* op = reinterpret_cast<float4*>(
            h_out + (size_t)(m0 + row) * F_ + lane * 8);
        op[0] = make_float4(hv[0], hv[1], hv[2], hv[3]);
        op[1] = make_float4(hv[4], hv[5], hv[6], hv[7]);
    }

    // ---- Phase 4 (layer 2 only): proj mini-GEMM + RQ spline ----
    if (layer == 2) {
        __syncthreads();   // both groups done with A/stag and h_out writes

        // rebuild A = h_out * mask (bf16 hi/lo); h_out rows are L2-hot
        {
            int row = tid >> 3;             // 0..63
            int q   = tid & 7;
            float mm = __ldg(&mask[m0 + row]);
            const float4* src = reinterpret_cast<const float4*>(
                h_out + (size_t)(m0 + row) * F_) + q * 8;
            #pragma unroll
            for (int j = 0; j < 8; j++) {
                float4 v = src[j];
                v.x *= mm; v.y *= mm; v.z *= mm; v.w *= mm;
                float hx = __bfloat162float(__float2bfloat16(v.x));
                float hy = __bfloat162float(__float2bfloat16(v.y));
                float hz = __bfloat162float(__float2bfloat16(v.z));
                float hw = __bfloat162float(__float2bfloat16(v.w));
                uint2 hp, lp;
                hp.x = pack_bf16x2(v.x, v.y);
                hp.y = pack_bf16x2(v.z, v.w);
                lp.x = pack_bf16x2(v.x - hx, v.y - hy);
                lp.y = pack_bf16x2(v.z - hz, v.w - hw);
                int c = (q * 8 + j) * 4;
                *reinterpret_cast<uint2*>(Ahi + row * AROW + c) = hp;
                *reinterpret_cast<uint2*>(Alo + row * AROW + c) = lp;
            }
        }
        __syncthreads();

        // mini-GEMM: 64x32, 16 warps = 4M x 4N, warp tile 16x8
        {
            const int pwm = wid >> 2;
            const int pwn = wid & 3;
            float pd[4] = {0.f, 0.f, 0.f, 0.f};

            const uint4* PB = g_Pfrag + ((size_t)pwn * 16) * 32 + lane;
            uint32_t pa_hi, pa_lo;
            {
                int r = lane & 15;
                int cb = (lane >> 4) * 16;
                int row = pwm * 16 + r;
                pa_hi = (uint32_t)__cvta_generic_to_shared(Ahi + row * AROW) + cb;
                pa_lo = (uint32_t)__cvta_generic_to_shared(Alo + row * AROW) + cb;
            }
            #pragma unroll 1
            for (int ks = 0; ks < 16; ks++) {
                uint4 bc = __ldg(&PB[ks * 32]);
                const uint32_t koff = ks * 32;
                uint32_t ah[4], al[4];
                ldmx4(ah, pa_hi + koff);
                ldmx4(al, pa_lo + koff);
                mma16816(pd, ah, bc.x, bc.y);
                mma16816(pd, ah, bc.z, bc.w);
                mma16816(pd, al, bc.x, bc.y);
            }
            int r0  = pwm * 16 + tg;
            int col = pwn * 8 + tq * 2;
            *reinterpret_cast<float2*>(&pstag[r0][col])     = make_float2(pd[0], pd[1]);
            *reinterpret_cast<float2*>(&pstag[r0 + 8][col]) = make_float2(pd[2], pd[3]);
        }
        __syncthreads();

        // spline: threads 0..63, one token each
        if (tid < 64) {
            int tok = m0 + tid;
            float m = __ldg(&mask[tok]);

            float proj[PROJ_];
            #pragma unroll
            for (int p = 0; p < PROJ_; p++)
                proj[p] = (pstag[tid][p] + __ldg(&b_proj[p])) * m;

            const float scale = 0.0625f;

            float cw[NB_ + 1], ww[NB_];
            {
                float mx = proj[0] * scale;
                #pragma unroll
                for (int j = 1; j < NB_; j++) mx = fmaxf(mx, proj[j] * scale);
                float e[NB_], sum = 0.f;
                #pragma unroll
                for (int j = 0; j < NB_; j++) { e[j] = expf(proj[j] * scale - mx); sum += e[j]; }
                float inv = 1.0f / sum;
                float cum = 0.f;
                cw[0] = -TBND;
                #pragma unroll
                for (int j = 0; j < NB_; j++) {
                    float wj = 0.001f + (1.0f - 0.001f * NB_) * (e[j] * inv);
                    cum += wj;
                    cw[j + 1] = 2.0f * TBND * cum - TBND;
                }
                cw[NB_] = TBND;
                #pragma unroll
                for (int j = 0; j < NB_; j++) ww[j] = cw[j + 1] - cw[j];
            }
            float ch[NB_ + 1], hh[NB_];
            {
                float mx = proj[NB_] * scale;
                #pragma unroll
                for (int j = 1; j < NB_; j++) mx = fmaxf(mx, proj[NB_ + j] * scale);
                float e[NB_], sum = 0.f;
                #pragma unroll
                for (int j = 0; j < NB_; j++) { e[j] = expf(proj[NB_ + j] * scale - mx); sum += e[j]; }
                float inv = 1.0f / sum;
                float cum = 0.f;
                ch[0] = -TBND;
                #pragma unroll
                for (int j = 0; j < NB_; j++) {
                    float hj = 0.001f + (1.0f - 0.001f * NB_) * (e[j] * inv);
                    cum += hj;
                    ch[j + 1] = 2.0f * TBND * cum - TBND;
                }
                ch[NB_] = TBND;
                #pragma unroll
                for (int j = 0; j < NB_; j++) hh[j] = ch[j + 1] - ch[j];
            }
            float dd[NB_ + 1];
            float cst = logf(expm1f(1.0f - 0.001f));
            dd[0]   = 0.001f + softplus_f(cst);
            dd[NB_] = dd[0];
            #pragma unroll
            for (int k = 1; k < NB_; k++) dd[k] = 0.001f + softplus_f(proj[2 * NB_ + k - 1]);

            float x1 = __ldg(&x[(size_t)tok * 2 + 1]);
            float xc = fminf(fmaxf(x1, -TBND), TBND);
            int idx = 0;
            #pragma unroll
            for (int j = 1; j <= NB_; j++) idx += (xc >= cw[j]) ? 1 : 0;
            if (idx > NB_ - 1) idx = NB_ - 1;

            float icw = cw[idx], ibw = ww[idx];
            float ich = ch[idx], ibh = hh[idx];
            float delta = ibh / ibw;
            float dk = dd[idx], dk1 = dd[idx + 1];
            float th   = (xc - icw) / ibw;
            float th1m = th * (1.0f - th);
            float denom = delta + (dk + dk1 - 2.0f * delta) * th1m;
            float num   = ibh * (delta * th * th + dk * th1m);
            float yv    = ich + num / denom;
            float omth  = 1.0f - th;
            float dnum  = delta * delta * (dk1 * th * th + 2.0f * delta * th1m + dk * omth * omth);
            float lad   = logf(dnum) - 2.0f * logf(denom);

            bool inside = (x1 >= -TBND) && (x1 <= TBND);
            float y1 = inside ? yv : x1;
            lad = inside ? lad : 0.0f;

            out[(size_t)tok * 2]     = __ldg(&x[(size_t)tok * 2]) * m;
            out[(size_t)tok * 2 + 1] = y1 * m;
            g_lad[tok] = lad * m;
        }
    }
}

// ---------------------------------------------------------------------------
// Kernel 5: deterministic per-batch logdet reduction
// ---------------------------------------------------------------------------
__global__ void logdet_kernel(float* __restrict__ out) {
    int b = blockIdx.x, tid = threadIdx.x;
    float s = 0.f;
    for (int j = tid; j < T_; j += 256) s += g_lad[b * T_ + j];
    __shared__ float sh[256];
    sh[tid] = s;
    __syncthreads();
    #pragma unroll
    for (int o = 128; o; o >>= 1) {
        if (tid < o) sh[tid] += sh[tid + o];
        __syncthreads();
    }
    if (tid == 0) out[(size_t)BT_ * 2 + b] = sh[0];
}

// ---------------------------------------------------------------------------
extern "C" void kernel_launch(void* const* d_in, const int* in_sizes, int n_in,
                              void* d_out, int out_size) {
    const float* x      = (const float*)d_in[0];
    const float* mask   = (const float*)d_in[1];
    const float* w_pre  = (const float*)d_in[2];
    const float* b_pre  = (const float*)d_in[3];
    const float* dw_k   = (const float*)d_in[4];
    const float* dw_b   = (const float*)d_in[5];
    const float* w11    = (const float*)d_in[6];
    const float* b11    = (const float*)d_in[7];
    const float* ln1g   = (const float*)d_in[8];
    const float* ln1b   = (const float*)d_in[9];
    const float* ln2g   = (const float*)d_in[10];
    const float* ln2b   = (const float*)d_in[11];
    const float* w_proj = (const float*)d_in[12];
    const float* b_proj = (const float*)d_in[13];
    float* out = (float*)d_out;

    cudaFuncSetAttribute(layer_fused_kernel,
                         cudaFuncAttributeMaxDynamicSharedMemorySize, GSMEM);

    prep_bfrag_kernel<<<NL_ * 32 * 16, 32>>>(w11);
    prep_pfrag_kernel<<<4 * 16, 32>>>(w_proj);

    int dil = 1;
    for (int i = 0; i < NL_; i++) {
        layer_fused_kernel<<<BT_ / 64, 512, GSMEM>>>(
            i, dil, x, mask, w_pre, b_pre,
            dw_k + (size_t)i * KS_ * F_,
            dw_b + (size_t)i * F_,
            ln1g + (size_t)i * F_,
            ln1b + (size_t)i * F_,
            b11 + (size_t)i * F_,
            ln2g + (size_t)i * F_,
            ln2b + (size_t)i * F_,
            b_proj, out);
        dil *= KS_;
    }

    logdet_kernel<<<B_, 256>>>(out);
}

// round 16
// speedup vs baseline: 1.0792x; 1.0792x over previous
#include <cuda_runtime.h>
#include <cuda_bf16.h>
#include <math.h>
#include <stdint.h>
#include <cstdint>

#define B_    16
#define T_    8192
#define F_    256
#define NL_   3
#define KS_   3
#define NB_   10
#define PROJ_ 29
#define BT_   (B_*T_)
#define TBND  5.0f

__device__ float g_h[(size_t)BT_ * F_];     // residual ping
__device__ float g_h2[(size_t)BT_ * F_];    // residual pong
__device__ float g_lad[BT_];
__device__ uint4 g_Bfrag[NL_ * 32 * 16 * 32];
__device__ uint4 g_Pfrag[4 * 16 * 32];

__device__ __forceinline__ float gelu_f(float v) {
    return 0.5f * v * (1.0f + erff(v * 0.7071067811865476f));
}

__device__ __forceinline__ float softplus_f(float v) {
    return fmaxf(v, 0.f) + log1pf(expf(-fabsf(v)));
}

__device__ __forceinline__ void mma16816(float* d, const uint32_t* a,
                                         uint32_t b0, uint32_t b1) {
    asm volatile(
        "mma.sync.aligned.m16n8k16.row.col.f32.bf16.bf16.f32 "
        "{%0,%1,%2,%3}, {%4,%5,%6,%7}, {%8,%9}, {%0,%1,%2,%3};"
        : "+f"(d[0]), "+f"(d[1]), "+f"(d[2]), "+f"(d[3])
        : "r"(a[0]), "r"(a[1]), "r"(a[2]), "r"(a[3]), "r"(b0), "r"(b1));
}

__device__ __forceinline__ void ldmx4(uint32_t* r, uint32_t addr) {
    asm volatile("ldmatrix.sync.aligned.m8n8.x4.shared.b16 {%0,%1,%2,%3}, [%4];"
        : "=r"(r[0]), "=r"(r[1]), "=r"(r[2]), "=r"(r[3]) : "r"(addr));
}

__device__ __forceinline__ uint32_t pack_bf16x2(float x, float y) {
    __nv_bfloat162 p = __halves2bfloat162(__float2bfloat16(x), __float2bfloat16(y));
    return *reinterpret_cast<uint32_t*>(&p);
}

// ---------------------------------------------------------------------------
// Kernel 0a: pack w11 into mma B fragments (hi/lo split)
// ---------------------------------------------------------------------------
__global__ void prep_bfrag_kernel(const float* __restrict__ w11) {
    int blk  = blockIdx.x;
    int lane = threadIdx.x;
    int ks   = blk & 15;
    int nt   = (blk >> 4) & 31;
    int l    = blk >> 9;
    int tg   = lane >> 2, tid = lane & 3;
    int n    = nt * 8 + tg;
    int k0   = ks * 16 + tid * 2;

    const float* w = w11 + (size_t)l * F_ * F_;
    float v00 = w[(size_t)(k0    ) * F_ + n];
    float v01 = w[(size_t)(k0 + 1) * F_ + n];
    float v10 = w[(size_t)(k0 + 8) * F_ + n];
    float v11 = w[(size_t)(k0 + 9) * F_ + n];

    float h00 = __bfloat162float(__float2bfloat16(v00));
    float h01 = __bfloat162float(__float2bfloat16(v01));
    float h10 = __bfloat162float(__float2bfloat16(v10));
    float h11 = __bfloat162float(__float2bfloat16(v11));

    uint4 o;
    o.x = pack_bf16x2(v00, v01);
    o.y = pack_bf16x2(v10, v11);
    o.z = pack_bf16x2(v00 - h00, v01 - h01);
    o.w = pack_bf16x2(v10 - h10, v11 - h11);
    g_Bfrag[(size_t)blk * 32 + lane] = o;
}

// ---------------------------------------------------------------------------
// Kernel 0b: pack w_proj [256,29] into fragments, N padded to 32
// ---------------------------------------------------------------------------
__global__ void prep_pfrag_kernel(const float* __restrict__ w_proj) {
    int blk  = blockIdx.x;
    int lane = threadIdx.x;
    int ks   = blk & 15;
    int nt   = blk >> 4;
    int tg   = lane >> 2, tid = lane & 3;
    int n    = nt * 8 + tg;
    int k0   = ks * 16 + tid * 2;

    float v00 = (n < PROJ_) ? w_proj[(size_t)(k0    ) * PROJ_ + n] : 0.f;
    float v01 = (n < PROJ_) ? w_proj[(size_t)(k0 + 1) * PROJ_ + n] : 0.f;
    float v10 = (n < PROJ_) ? w_proj[(size_t)(k0 + 8) * PROJ_ + n] : 0.f;
    float v11 = (n < PROJ_) ? w_proj[(size_t)(k0 + 9) * PROJ_ + n] : 0.f;

    float h00 = __bfloat162float(__float2bfloat16(v00));
    float h01 = __bfloat162float(__float2bfloat16(v01));
    float h10 = __bfloat162float(__float2bfloat16(v10));
    float h11 = __bfloat162float(__float2bfloat16(v11));

    uint4 o;
    o.x = pack_bf16x2(v00, v01);
    o.y = pack_bf16x2(v10, v11);
    o.z = pack_bf16x2(v00 - h00, v01 - h01);
    o.w = pack_bf16x2(v10 - h10, v11 - h11);
    g_Pfrag[(size_t)blk * 32 + lane] = o;
}

// ---------------------------------------------------------------------------
// Kernel 1: FUSED layer (M=64, 512 threads, 2 CTAs/SM).
// layer==2 additionally runs phase 4: proj mini-GEMM + RQ spline -> out/g_lad.
// ---------------------------------------------------------------------------
#define AROW    264
#define GSMEM   (2 * 64 * AROW * 2 + 256)

__global__ void __launch_bounds__(512, 2)
layer_fused_kernel(int layer, int dil,
                   const float* __restrict__ x,
                   const float* __restrict__ mask,
                   const float* __restrict__ w_pre,
                   const float* __restrict__ b_pre,
                   const float* __restrict__ dwk,
                   const float* __restrict__ dwb,
                   const float* __restrict__ g1,
                   const float* __restrict__ b1,
                   const float* __restrict__ b11,
                   const float* __restrict__ g2,
                   const float* __restrict__ b2,
                   const float* __restrict__ b_proj,
                   float* __restrict__ out) {
    extern __shared__ char dyn[];
    __shared__ float4 s_k[3][64], s_b[64], s_g[64], s_bb[64], s_wp[64], s_bp[64];
    __shared__ float pstag[64][34];

    char* basep = (char*)(((uintptr_t)dyn + 15) & ~(uintptr_t)15);
    __nv_bfloat16* Ahi = reinterpret_cast<__nv_bfloat16*>(basep);
    __nv_bfloat16* Alo = Ahi + 64 * AROW;
    float* stag = reinterpret_cast<float*>(basep);
    const int SROW = 260;

    const int tid  = threadIdx.x;
    const int wid  = tid >> 5;
    const int lane = tid & 31;
    const int tg   = lane >> 2, tq = lane & 3;
    const int wm   = wid >> 3;
    const int wn   = wid & 7;
    const int m0   = blockIdx.x * 64;

    const float* h_in  = (layer == 1) ? g_h : g_h2;
    float*       h_out = (layer == 1) ? g_h2 : g_h;

    // ---- stage params ----
    if (tid < 64) {
        s_k[0][tid] = reinterpret_cast<const float4*>(dwk)[tid];
        s_k[1][tid] = reinterpret_cast<const float4*>(dwk)[64 + tid];
        s_k[2][tid] = reinterpret_cast<const float4*>(dwk)[128 + tid];
        s_wp[tid]   = reinterpret_cast<const float4*>(w_pre)[tid];
    } else if (tid < 128) {
        s_b[tid - 64]  = reinterpret_cast<const float4*>(dwb)[tid - 64];
        s_bp[tid - 64] = reinterpret_cast<const float4*>(b_pre)[tid - 64];
    } else if (tid < 192) {
        s_g[tid - 128] = reinterpret_cast<const float4*>(g1)[tid - 128];
    } else if (tid < 256) {
        s_bb[tid - 192] = reinterpret_cast<const float4*>(b1)[tid - 192];
    }
    __syncthreads();

    // ---- Phase 1: conv + LN1 + gelu -> A SMEM (bf16 hi/lo); 4 rows/warp ----
    #pragma unroll 1
    for (int i = 0; i < 4; i++) {
        int r   = wid * 4 + i;
        int tok = m0 + r;
        int t   = tok & (T_ - 1);

        float a[8];
        {
            float4 b0 = s_b[lane], b1v = s_b[lane + 32];
            a[0]=b0.x; a[1]=b0.y; a[2]=b0.z; a[3]=b0.w;
            a[4]=b1v.x; a[5]=b1v.y; a[6]=b1v.z; a[7]=b1v.w;
        }

        #pragma unroll
        for (int tap = 0; tap < 3; tap++) {
            int off = (tap - 1) * dil;
            int tt  = t + off;
            if (tt >= 0 && tt < T_) {
                float mm = __ldg(&mask[tok + off]);
                float4 k0 = s_k[tap][lane], k1 = s_k[tap][lane + 32];
                float karr[8] = {k0.x,k0.y,k0.z,k0.w,k1.x,k1.y,k1.z,k1.w};
                if (layer == 0) {
                    float x0 = __ldg(&x[(size_t)(tok + off) * 2]);
                    float4 w0 = s_wp[lane], w1 = s_wp[lane + 32];
                    float4 p0 = s_bp[lane], p1 = s_bp[lane + 32];
                    float wpar[8] = {w0.x,w0.y,w0.z,w0.w,w1.x,w1.y,w1.z,w1.w};
                    float bpar[8] = {p0.x,p0.y,p0.z,p0.w,p1.x,p1.y,p1.z,p1.w};
                    float xm = x0 * mm;
                    #pragma unroll
                    for (int j = 0; j < 8; j++)
                        a[j] += (xm * wpar[j] + mm * bpar[j]) * karr[j];
                } else {
                    const float4* hr = reinterpret_cast<const float4*>(
                        h_in + (size_t)(tok + off) * F_);
                    float4 h0 = hr[lane], h1 = hr[lane + 32];
                    a[0] += h0.x * mm * karr[0]; a[1] += h0.y * mm * karr[1];
                    a[2] += h0.z * mm * karr[2]; a[3] += h0.w * mm * karr[3];
                    a[4] += h1.x * mm * karr[4]; a[5] += h1.y * mm * karr[5];
                    a[6] += h1.z * mm * karr[6]; a[7] += h1.w * mm * karr[7];
                }
            }
        }

        float s = 0.f, ss = 0.f;
        #pragma unroll
        for (int j = 0; j < 8; j++) { s += a[j]; ss += a[j] * a[j]; }
        #pragma unroll
        for (int o = 16; o; o >>= 1) {
            s  += __shfl_xor_sync(0xFFFFFFFFu, s,  o);
            ss += __shfl_xor_sync(0xFFFFFFFFu, ss, o);
        }
        float mean = s * (1.0f / F_);
        float rstd = rsqrtf(ss * (1.0f / F_) - mean * mean + 1e-5f);

        float4 gg0 = s_g[lane], gg1 = s_g[lane + 32];
        float4 bb0 = s_bb[lane], bb1 = s_bb[lane + 32];
        float garr[8] = {gg0.x,gg0.y,gg0.z,gg0.w,gg1.x,gg1.y,gg1.z,gg1.w};
        float barr[8] = {bb0.x,bb0.y,bb0.z,bb0.w,bb1.x,bb1.y,bb1.z,bb1.w};

        float rv[8];
        #pragma unroll
        for (int j = 0; j < 8; j++) {
            float v = (a[j] - mean) * rstd * garr[j] + barr[j];
            rv[j] = gelu_f(v);
        }
        uint2 hp0, lp0, hp1, lp1;
        float h0 = __bfloat162float(__float2bfloat16(rv[0]));
        float h1v = __bfloat162float(__float2bfloat16(rv[1]));
        float h2 = __bfloat162float(__float2bfloat16(rv[2]));
        float h3 = __bfloat162float(__float2bfloat16(rv[3]));
        float h4 = __bfloat162float(__float2bfloat16(rv[4]));
        float h5 = __bfloat162float(__float2bfloat16(rv[5]));
        float h6 = __bfloat162float(__float2bfloat16(rv[6]));
        float h7 = __bfloat162float(__float2bfloat16(rv[7]));
        hp0.x = pack_bf16x2(rv[0], rv[1]);  hp0.y = pack_bf16x2(rv[2], rv[3]);
        lp0.x = pack_bf16x2(rv[0]-h0, rv[1]-h1v); lp0.y = pack_bf16x2(rv[2]-h2, rv[3]-h3);
        hp1.x = pack_bf16x2(rv[4], rv[5]);  hp1.y = pack_bf16x2(rv[6], rv[7]);
        lp1.x = pack_bf16x2(rv[4]-h4, rv[5]-h5); lp1.y = pack_bf16x2(rv[6]-h6, rv[7]-h7);
        *reinterpret_cast<uint2*>(Ahi + r * AROW + 4*lane)       = hp0;
        *reinterpret_cast<uint2*>(Alo + r * AROW + 4*lane)       = lp0;
        *reinterpret_cast<uint2*>(Ahi + r * AROW + 128 + 4*lane) = hp1;
        *reinterpret_cast<uint2*>(Alo + r * AROW + 128 + 4*lane) = lp1;
    }
    __syncthreads();

    // ---- Phase 2: mainloop (B via __ldg, term-major, unroll-4 pipelining) ----
    float d[2][4][4];
    #pragma unroll
    for (int mt = 0; mt < 2; mt++)
        #pragma unroll
        for (int nt = 0; nt < 4; nt++)
            #pragma unroll
            for (int q = 0; q < 4; q++) d[mt][nt][q] = 0.f;

    const uint4* Bbase = g_Bfrag + ((size_t)(layer * 32 + wn * 4) * 16) * 32 + lane;

    uint32_t a_hi_addr[2], a_lo_addr[2];
    {
        int r = lane & 15;
        int cb = (lane >> 4) * 16;
        #pragma unroll
        for (int mt = 0; mt < 2; mt++) {
            int row = wm * 32 + mt * 16 + r;
            a_hi_addr[mt] = (uint32_t)__cvta_generic_to_shared(Ahi + row * AROW) + cb;
            a_lo_addr[mt] = (uint32_t)__cvta_generic_to_shared(Alo + row * AROW) + cb;
        }
    }

    #pragma unroll 4
    for (int ks = 0; ks < 16; ks++) {
        uint4 bcur[4];
        #pragma unroll
        for (int nt = 0; nt < 4; nt++)
            bcur[nt] = __ldg(&Bbase[(nt * 16 + ks) * 32]);
        const uint32_t koff = ks * 32;
        #pragma unroll
        for (int mt = 0; mt < 2; mt++) {
            uint32_t ah[4], al[4];
            ldmx4(ah, a_hi_addr[mt] + koff);
            ldmx4(al, a_lo_addr[mt] + koff);
            #pragma unroll
            for (int nt = 0; nt < 4; nt++)
                mma16816(d[mt][nt], ah, bcur[nt].x, bcur[nt].y);
            #pragma unroll
            for (int nt = 0; nt < 4; nt++)
                mma16816(d[mt][nt], ah, bcur[nt].z, bcur[nt].w);
            #pragma unroll
            for (int nt = 0; nt < 4; nt++)
                mma16816(d[mt][nt], al, bcur[nt].x, bcur[nt].y);
        }
    }

    // ---- stage accum ----
    __syncthreads();
    #pragma unroll
    for (int mt = 0; mt < 2; mt++) {
        int r0 = wm * 32 + mt * 16 + tg;
        #pragma unroll
        for (int nt = 0; nt < 4; nt++) {
            int col = wn * 32 + nt * 8 + tq * 2;
            *reinterpret_cast<float2*>(&stag[r0 * SROW + col]) =
                make_float2(d[mt][nt][0], d[mt][nt][1]);
            *reinterpret_cast<float2*>(&stag[(r0 + 8) * SROW + col]) =
                make_float2(d[mt][nt][2], d[mt][nt][3]);
        }
    }
    __syncthreads();

    // ---- Phase 3: LN2 + gelu + residual -> h_out; 4 rows/warp ----
    #pragma unroll 1
    for (int i = 0; i < 4; i++) {
        int row = wid * 4 + i;
        float4 f0 = *reinterpret_cast<const float4*>(&stag[row * SROW + lane * 8]);
        float4 f1 = *reinterpret_cast<const float4*>(&stag[row * SROW + lane * 8 + 4]);
        float4 bb0 = reinterpret_cast<const float4*>(b11)[lane * 2];
        float4 bb1 = reinterpret_cast<const float4*>(b11)[lane * 2 + 1];
        float v[8] = {f0.x + bb0.x, f0.y + bb0.y, f0.z + bb0.z, f0.w + bb0.w,
                      f1.x + bb1.x, f1.y + bb1.y, f1.z + bb1.z, f1.w + bb1.w};
        float s = 0.f, ss = 0.f;
        #pragma unroll
        for (int j = 0; j < 8; j++) { s += v[j]; ss += v[j] * v[j]; }
        #pragma unroll
        for (int o = 16; o; o >>= 1) {
            s  += __shfl_xor_sync(0xFFFFFFFFu, s,  o);
            ss += __shfl_xor_sync(0xFFFFFFFFu, ss, o);
        }
        float mean = s * (1.0f / F_);
        float rstd = rsqrtf(ss * (1.0f / F_) - mean * mean + 1e-5f);

        float4 gg0 = reinterpret_cast<const float4*>(g2)[lane * 2];
        float4 gg1 = reinterpret_cast<const float4*>(g2)[lane * 2 + 1];
        float4 zb0 = reinterpret_cast<const float4*>(b2)[lane * 2];
        float4 zb1 = reinterpret_cast<const float4*>(b2)[lane * 2 + 1];
        float garr[8] = {gg0.x,gg0.y,gg0.z,gg0.w,gg1.x,gg1.y,gg1.z,gg1.w};
        float barr[8] = {zb0.x,zb0.y,zb0.z,zb0.w,zb1.x,zb1.y,zb1.z,zb1.w};

        float hv[8];
        if (layer == 0) {
            float x0 = __ldg(&x[(size_t)(m0 + row) * 2]);
            float4 w0 = s_wp[lane * 2], w1 = s_wp[lane * 2 + 1];
            float4 p0 = s_bp[lane * 2], p1 = s_bp[lane * 2 + 1];
            hv[0] = x0*w0.x + p0.x; hv[1] = x0*w0.y + p0.y;
            hv[2] = x0*w0.z + p0.z; hv[3] = x0*w0.w + p0.w;
            hv[4] = x0*w1.x + p1.x; hv[5] = x0*w1.y + p1.y;
            hv[6] = x0*w1.z + p1.z; hv[7] = x0*w1.w + p1.w;
        } else {
            const float4* hp = reinterpret_cast<const float4*>(
                h_in + (size_t)(m0 + row) * F_ + lane * 8);
            float4 h0 = hp[0], h1 = hp[1];
            hv[0]=h0.x; hv[1]=h0.y; hv[2]=h0.z; hv[3]=h0.w;
            hv[4]=h1.x; hv[5]=h1.y; hv[6]=h1.z; hv[7]=h1.w;
        }
        #pragma unroll
        for (int j = 0; j < 8; j++) {
            float z = (v[j] - mean) * rstd * garr[j] + barr[j];
            hv[j] += gelu_f(z);
        }
        float4* op = reinterpret_cast<float4*>(
            h_out + (size_t)(m0 + row) * F_ + lane * 8);
        op[0] = make_float4(hv[0], hv[1], hv[2], hv[3]);
        op[1] = make_float4(hv[4], hv[5], hv[6], hv[7]);
    }

    // ---- Phase 4 (layer 2 only): proj mini-GEMM + RQ spline ----
    if (layer == 2) {
        __syncthreads();   // all stag reads/h_out writes done; safe to reuse A

        // rebuild A = h_out * mask (bf16 hi/lo); h_out rows are L2-hot
        {
            int row = tid >> 3;             // 0..63
            int q   = tid & 7;              // 8 float4 per thread
            float mm = __ldg(&mask[m0 + row]);
            const float4* src = reinterpret_cast<const float4*>(
                h_out + (size_t)(m0 + row) * F_) + q * 8;
            #pragma unroll
            for (int j = 0; j < 8; j++) {
                float4 v = src[j];
                v.x *= mm; v.y *= mm; v.z *= mm; v.w *= mm;
                float hx = __bfloat162float(__float2bfloat16(v.x));
                float hy = __bfloat162float(__float2bfloat16(v.y));
                float hz = __bfloat162float(__float2bfloat16(v.z));
                float hw = __bfloat162float(__float2bfloat16(v.w));
                uint2 hp, lp;
                hp.x = pack_bf16x2(v.x, v.y);
                hp.y = pack_bf16x2(v.z, v.w);
                lp.x = pack_bf16x2(v.x - hx, v.y - hy);
                lp.y = pack_bf16x2(v.z - hz, v.w - hw);
                int c = (q * 8 + j) * 4;
                *reinterpret_cast<uint2*>(Ahi + row * AROW + c) = hp;
                *reinterpret_cast<uint2*>(Alo + row * AROW + c) = lp;
            }
        }
        __syncthreads();

        // mini-GEMM: 64x32, 16 warps = 4M x 4N, warp tile 16x8
        {
            const int pwm = wid >> 2;       // 0..3
            const int pwn = wid & 3;        // 0..3
            float pd[4] = {0.f, 0.f, 0.f, 0.f};

            const uint4* PB = g_Pfrag + ((size_t)pwn * 16) * 32 + lane;
            uint32_t pa_hi, pa_lo;
            {
                int r = lane & 15;
                int cb = (lane >> 4) * 16;
                int row = pwm * 16 + r;
                pa_hi = (uint32_t)__cvta_generic_to_shared(Ahi + row * AROW) + cb;
                pa_lo = (uint32_t)__cvta_generic_to_shared(Alo + row * AROW) + cb;
            }
            #pragma unroll 1
            for (int ks = 0; ks < 16; ks++) {
                uint4 bc = __ldg(&PB[ks * 32]);
                const uint32_t koff = ks * 32;
                uint32_t ah[4], al[4];
                ldmx4(ah, pa_hi + koff);
                ldmx4(al, pa_lo + koff);
                mma16816(pd, ah, bc.x, bc.y);
                mma16816(pd, ah, bc.z, bc.w);
                mma16816(pd, al, bc.x, bc.y);
            }
            int r0  = pwm * 16 + tg;
            int col = pwn * 8 + tq * 2;
            *reinterpret_cast<float2*>(&pstag[r0][col])     = make_float2(pd[0], pd[1]);
            *reinterpret_cast<float2*>(&pstag[r0 + 8][col]) = make_float2(pd[2], pd[3]);
        }
        __syncthreads();

        // spline: threads 0..63, one token each
        if (tid < 64) {
            int tok = m0 + tid;
            float m = __ldg(&mask[tok]);

            float proj[PROJ_];
            #pragma unroll
            for (int p = 0; p < PROJ_; p++)
                proj[p] = (pstag[tid][p] + __ldg(&b_proj[p])) * m;

            const float scale = 0.0625f;

            float cw[NB_ + 1], ww[NB_];
            {
                float mx = proj[0] * scale;
                #pragma unroll
                for (int j = 1; j < NB_; j++) mx = fmaxf(mx, proj[j] * scale);
                float e[NB_], sum = 0.f;
                #pragma unroll
                for (int j = 0; j < NB_; j++) { e[j] = expf(proj[j] * scale - mx); sum += e[j]; }
                float inv = 1.0f / sum;
                float cum = 0.f;
                cw[0] = -TBND;
                #pragma unroll
                for (int j = 0; j < NB_; j++) {
                    float wj = 0.001f + (1.0f - 0.001f * NB_) * (e[j] * inv);
                    cum += wj;
                    cw[j + 1] = 2.0f * TBND * cum - TBND;
                }
                cw[NB_] = TBND;
                #pragma unroll
                for (int j = 0; j < NB_; j++) ww[j] = cw[j + 1] - cw[j];
            }
            float ch[NB_ + 1], hh[NB_];
            {
                float mx = proj[NB_] * scale;
                #pragma unroll
                for (int j = 1; j < NB_; j++) mx = fmaxf(mx, proj[NB_ + j] * scale);
                float e[NB_], sum = 0.f;
                #pragma unroll
                for (int j = 0; j < NB_; j++) { e[j] = expf(proj[NB_ + j] * scale - mx); sum += e[j]; }
                float inv = 1.0f / sum;
                float cum = 0.f;
                ch[0] = -TBND;
                #pragma unroll
                for (int j = 0; j < NB_; j++) {
                    float hj = 0.001f + (1.0f - 0.001f * NB_) * (e[j] * inv);
                    cum += hj;
                    ch[j + 1] = 2.0f * TBND * cum - TBND;
                }
                ch[NB_] = TBND;
                #pragma unroll
                for (int j = 0; j < NB_; j++) hh[j] = ch[j + 1] - ch[j];
            }
            float dd[NB_ + 1];
            float cst = logf(expm1f(1.0f - 0.001f));
            dd[0]   = 0.001f + softplus_f(cst);
            dd[NB_] = dd[0];
            #pragma unroll
            for (int k = 1; k < NB_; k++) dd[k] = 0.001f + softplus_f(proj[2 * NB_ + k - 1]);

            float x1 = __ldg(&x[(size_t)tok * 2 + 1]);
            float xc = fminf(fmaxf(x1, -TBND), TBND);
            int idx = 0;
            #pragma unroll
            for (int j = 1; j <= NB_; j++) idx += (xc >= cw[j]) ? 1 : 0;
            if (idx > NB_ - 1) idx = NB_ - 1;

            float icw = cw[idx], ibw = ww[idx];
            float ich = ch[idx], ibh = hh[idx];
            float delta = ibh / ibw;
            float dk = dd[idx], dk1 = dd[idx + 1];
            float th   = (xc - icw) / ibw;
            float th1m = th * (1.0f - th);
            float denom = delta + (dk + dk1 - 2.0f * delta) * th1m;
            float num   = ibh * (delta * th * th + dk * th1m);
            float yv    = ich + num / denom;
            float omth  = 1.0f - th;
            float dnum  = delta * delta * (dk1 * th * th + 2.0f * delta * th1m + dk * omth * omth);
            float lad   = logf(dnum) - 2.0f * logf(denom);

            bool inside = (x1 >= -TBND) && (x1 <= TBND);
            float y1 = inside ? yv : x1;
            lad = inside ? lad : 0.0f;

            out[(size_t)tok * 2]     = __ldg(&x[(size_t)tok * 2]) * m;
            out[(size_t)tok * 2 + 1] = y1 * m;
            g_lad[tok] = lad * m;
        }
    }
}

// ---------------------------------------------------------------------------
// Kernel 5: deterministic per-batch logdet reduction
// ---------------------------------------------------------------------------
__global__ void logdet_kernel(float* __restrict__ out) {
    int b = blockIdx.x, tid = threadIdx.x;
    float s = 0.f;
    for (int j = tid; j < T_; j += 256) s += g_lad[b * T_ + j];
    __shared__ float sh[256];
    sh[tid] = s;
    __syncthreads();
    #pragma unroll
    for (int o = 128; o; o >>= 1) {
        if (tid < o) sh[tid] += sh[tid + o];
        __syncthreads();
    }
    if (tid == 0) out[(size_t)BT_ * 2 + b] = sh[0];
}

// ---------------------------------------------------------------------------
extern "C" void kernel_launch(void* const* d_in, const int* in_sizes, int n_in,
                              void* d_out, int out_size) {
    const float* x      = (const float*)d_in[0];
    const float* mask   = (const float*)d_in[1];
    const float* w_pre  = (const float*)d_in[2];
    const float* b_pre  = (const float*)d_in[3];
    const float* dw_k   = (const float*)d_in[4];
    const float* dw_b   = (const float*)d_in[5];
    const float* w11    = (const float*)d_in[6];
    const float* b11    = (const float*)d_in[7];
    const float* ln1g   = (const float*)d_in[8];
    const float* ln1b   = (const float*)d_in[9];
    const float* ln2g   = (const float*)d_in[10];
    const float* ln2b   = (const float*)d_in[11];
    const float* w_proj = (const float*)d_in[12];
    const float* b_proj = (const float*)d_in[13];
    float* out = (float*)d_out;

    cudaFuncSetAttribute(layer_fused_kernel,
                         cudaFuncAttributeMaxDynamicSharedMemorySize, GSMEM);

    prep_bfrag_kernel<<<NL_ * 32 * 16, 32>>>(w11);
    prep_pfrag_kernel<<<4 * 16, 32>>>(w_proj);

    int dil = 1;
    for (int i = 0; i < NL_; i++) {
        layer_fused_kernel<<<BT_ / 64, 512, GSMEM>>>(
            i, dil, x, mask, w_pre, b_pre,
            dw_k + (size_t)i * KS_ * F_,
            dw_b + (size_t)i * F_,
            ln1g + (size_t)i * F_,
            ln1b + (size_t)i * F_,
            b11 + (size_t)i * F_,
            ln2g + (size_t)i * F_,
            ln2b + (size_t)i * F_,
            b_proj, out);
        dil *= KS_;
    }

    logdet_kernel<<<B_, 256>>>(out);
}

// round 17
// speedup vs baseline: 1.2484x; 1.1569x over previous
#include <cuda_runtime.h>
#include <cuda_bf16.h>
#include <cuda_fp16.h>
#include <math.h>
#include <stdint.h>
#include <cstdint>

#define B_    16
#define T_    8192
#define F_    256
#define NL_   3
#define KS_   3
#define NB_   10
#define PROJ_ 29
#define BT_   (B_*T_)
#define TBND  5.0f

__device__ float g_h[(size_t)BT_ * F_];     // residual ping
__device__ float g_h2[(size_t)BT_ * F_];    // residual pong
__device__ float g_lad[BT_];
__device__ uint4 g_Bfrag[NL_ * 32 * 16 * 32];
__device__ uint4 g_Pfrag[4 * 16 * 32];

__device__ __forceinline__ float gelu_f(float v) {
    return 0.5f * v * (1.0f + erff(v * 0.7071067811865476f));
}

__device__ __forceinline__ float softplus_f(float v) {
    return fmaxf(v, 0.f) + log1pf(expf(-fabsf(v)));
}

// fp16 mma, fp32 accumulate
__device__ __forceinline__ void mma16816(float* d, const uint32_t* a,
                                         uint32_t b0, uint32_t b1) {
    asm volatile(
        "mma.sync.aligned.m16n8k16.row.col.f32.f16.f16.f32 "
        "{%0,%1,%2,%3}, {%4,%5,%6,%7}, {%8,%9}, {%0,%1,%2,%3};"
        : "+f"(d[0]), "+f"(d[1]), "+f"(d[2]), "+f"(d[3])
        : "r"(a[0]), "r"(a[1]), "r"(a[2]), "r"(a[3]), "r"(b0), "r"(b1));
}

__device__ __forceinline__ void ldmx4(uint32_t* r, uint32_t addr) {
    asm volatile("ldmatrix.sync.aligned.m8n8.x4.shared.b16 {%0,%1,%2,%3}, [%4];"
        : "=r"(r[0]), "=r"(r[1]), "=r"(r[2]), "=r"(r[3]) : "r"(addr));
}

__device__ __forceinline__ uint32_t pack_f16x2(float x, float y) {
    __half2 p = __halves2half2(__float2half(x), __float2half(y));
    return *reinterpret_cast<uint32_t*>(&p);
}

// ---------------------------------------------------------------------------
// Kernel 0a: pack w11 into mma B fragments (fp16 hi/lo split)
// ---------------------------------------------------------------------------
__global__ void prep_bfrag_kernel(const float* __restrict__ w11) {
    int blk  = blockIdx.x;
    int lane = threadIdx.x;
    int ks   = blk & 15;
    int nt   = (blk >> 4) & 31;
    int l    = blk >> 9;
    int tg   = lane >> 2, tid = lane & 3;
    int n    = nt * 8 + tg;
    int k0   = ks * 16 + tid * 2;

    const float* w = w11 + (size_t)l * F_ * F_;
    float v00 = w[(size_t)(k0    ) * F_ + n];
    float v01 = w[(size_t)(k0 + 1) * F_ + n];
    float v10 = w[(size_t)(k0 + 8) * F_ + n];
    float v11 = w[(size_t)(k0 + 9) * F_ + n];

    float h00 = __half2float(__float2half(v00));
    float h01 = __half2float(__float2half(v01));
    float h10 = __half2float(__float2half(v10));
    float h11 = __half2float(__float2half(v11));

    uint4 o;
    o.x = pack_f16x2(v00, v01);
    o.y = pack_f16x2(v10, v11);
    o.z = pack_f16x2(v00 - h00, v01 - h01);
    o.w = pack_f16x2(v10 - h10, v11 - h11);
    g_Bfrag[(size_t)blk * 32 + lane] = o;
}

// ---------------------------------------------------------------------------
// Kernel 0b: pack w_proj [256,29] into fp16 hi/lo fragments, N padded to 32
// ---------------------------------------------------------------------------
__global__ void prep_pfrag_kernel(const float* __restrict__ w_proj) {
    int blk  = blockIdx.x;
    int lane = threadIdx.x;
    int ks   = blk & 15;
    int nt   = blk >> 4;
    int tg   = lane >> 2, tid = lane & 3;
    int n    = nt * 8 + tg;
    int k0   = ks * 16 + tid * 2;

    float v00 = (n < PROJ_) ? w_proj[(size_t)(k0    ) * PROJ_ + n] : 0.f;
    float v01 = (n < PROJ_) ? w_proj[(size_t)(k0 + 1) * PROJ_ + n] : 0.f;
    float v10 = (n < PROJ_) ? w_proj[(size_t)(k0 + 8) * PROJ_ + n] : 0.f;
    float v11 = (n < PROJ_) ? w_proj[(size_t)(k0 + 9) * PROJ_ + n] : 0.f;

    float h00 = __half2float(__float2half(v00));
    float h01 = __half2float(__float2half(v01));
    float h10 = __half2float(__float2half(v10));
    float h11 = __half2float(__float2half(v11));

    uint4 o;
    o.x = pack_f16x2(v00, v01);
    o.y = pack_f16x2(v10, v11);
    o.z = pack_f16x2(v00 - h00, v01 - h01);
    o.w = pack_f16x2(v10 - h10, v11 - h11);
    g_Pfrag[(size_t)blk * 32 + lane] = o;
}

// ---------------------------------------------------------------------------
// Kernel 1: FUSED layer (M=64, 512 threads, 2 CTAs/SM), fp16 2-term split.
// layer==2 additionally runs phase 4: proj mini-GEMM + RQ spline.
// ---------------------------------------------------------------------------
#define AROW    264
#define GSMEM   (2 * 64 * AROW * 2 + 256)   // keep old size: stag reuses it

__global__ void __launch_bounds__(512, 2)
layer_fused_kernel(int layer, int dil,
                   const float* __restrict__ x,
                   const float* __restrict__ mask,
                   const float* __restrict__ w_pre,
                   const float* __restrict__ b_pre,
                   const float* __restrict__ dwk,
                   const float* __restrict__ dwb,
                   const float* __restrict__ g1,
                   const float* __restrict__ b1,
                   const float* __restrict__ b11,
                   const float* __restrict__ g2,
                   const float* __restrict__ b2,
                   const float* __restrict__ b_proj,
                   float* __restrict__ out) {
    extern __shared__ char dyn[];
    __shared__ float4 s_k[3][64], s_b[64], s_g[64], s_bb[64], s_wp[64], s_bp[64];
    __shared__ float pstag[64][34];

    char* basep = (char*)(((uintptr_t)dyn + 15) & ~(uintptr_t)15);
    __half* Ahi = reinterpret_cast<__half*>(basep);
    float* stag = reinterpret_cast<float*>(basep);
    const int SROW = 260;

    const int tid  = threadIdx.x;
    const int wid  = tid >> 5;
    const int lane = tid & 31;
    const int tg   = lane >> 2, tq = lane & 3;
    const int wm   = wid >> 3;
    const int wn   = wid & 7;
    const int m0   = blockIdx.x * 64;

    const float* h_in  = (layer == 1) ? g_h : g_h2;
    float*       h_out = (layer == 1) ? g_h2 : g_h;

    // ---- stage params ----
    if (tid < 64) {
        s_k[0][tid] = reinterpret_cast<const float4*>(dwk)[tid];
        s_k[1][tid] = reinterpret_cast<const float4*>(dwk)[64 + tid];
        s_k[2][tid] = reinterpret_cast<const float4*>(dwk)[128 + tid];
        s_wp[tid]   = reinterpret_cast<const float4*>(w_pre)[tid];
    } else if (tid < 128) {
        s_b[tid - 64]  = reinterpret_cast<const float4*>(dwb)[tid - 64];
        s_bp[tid - 64] = reinterpret_cast<const float4*>(b_pre)[tid - 64];
    } else if (tid < 192) {
        s_g[tid - 128] = reinterpret_cast<const float4*>(g1)[tid - 128];
    } else if (tid < 256) {
        s_bb[tid - 192] = reinterpret_cast<const float4*>(b1)[tid - 192];
    }
    __syncthreads();

    // ---- Phase 1: conv + LN1 + gelu -> A SMEM (fp16); 4 rows/warp ----
    #pragma unroll 1
    for (int i = 0; i < 4; i++) {
        int r   = wid * 4 + i;
        int tok = m0 + r;
        int t   = tok & (T_ - 1);

        float a[8];
        {
            float4 b0 = s_b[lane], b1v = s_b[lane + 32];
            a[0]=b0.x; a[1]=b0.y; a[2]=b0.z; a[3]=b0.w;
            a[4]=b1v.x; a[5]=b1v.y; a[6]=b1v.z; a[7]=b1v.w;
        }

        #pragma unroll
        for (int tap = 0; tap < 3; tap++) {
            int off = (tap - 1) * dil;
            int tt  = t + off;
            if (tt >= 0 && tt < T_) {
                float mm = __ldg(&mask[tok + off]);
                float4 k0 = s_k[tap][lane], k1 = s_k[tap][lane + 32];
                float karr[8] = {k0.x,k0.y,k0.z,k0.w,k1.x,k1.y,k1.z,k1.w};
                if (layer == 0) {
                    float x0 = __ldg(&x[(size_t)(tok + off) * 2]);
                    float4 w0 = s_wp[lane], w1 = s_wp[lane + 32];
                    float4 p0 = s_bp[lane], p1 = s_bp[lane + 32];
                    float wpar[8] = {w0.x,w0.y,w0.z,w0.w,w1.x,w1.y,w1.z,w1.w};
                    float bpar[8] = {p0.x,p0.y,p0.z,p0.w,p1.x,p1.y,p1.z,p1.w};
                    float xm = x0 * mm;
                    #pragma unroll
                    for (int j = 0; j < 8; j++)
                        a[j] += (xm * wpar[j] + mm * bpar[j]) * karr[j];
                } else {
                    const float4* hr = reinterpret_cast<const float4*>(
                        h_in + (size_t)(tok + off) * F_);
                    float4 h0 = hr[lane], h1 = hr[lane + 32];
                    a[0] += h0.x * mm * karr[0]; a[1] += h0.y * mm * karr[1];
                    a[2] += h0.z * mm * karr[2]; a[3] += h0.w * mm * karr[3];
                    a[4] += h1.x * mm * karr[4]; a[5] += h1.y * mm * karr[5];
                    a[6] += h1.z * mm * karr[6]; a[7] += h1.w * mm * karr[7];
                }
            }
        }

        float s = 0.f, ss = 0.f;
        #pragma unroll
        for (int j = 0; j < 8; j++) { s += a[j]; ss += a[j] * a[j]; }
        #pragma unroll
        for (int o = 16; o; o >>= 1) {
            s  += __shfl_xor_sync(0xFFFFFFFFu, s,  o);
            ss += __shfl_xor_sync(0xFFFFFFFFu, ss, o);
        }
        float mean = s * (1.0f / F_);
        float rstd = rsqrtf(ss * (1.0f / F_) - mean * mean + 1e-5f);

        float4 gg0 = s_g[lane], gg1 = s_g[lane + 32];
        float4 bb0 = s_bb[lane], bb1 = s_bb[lane + 32];
        float garr[8] = {gg0.x,gg0.y,gg0.z,gg0.w,gg1.x,gg1.y,gg1.z,gg1.w};
        float barr[8] = {bb0.x,bb0.y,bb0.z,bb0.w,bb1.x,bb1.y,bb1.z,bb1.w};

        float rv[8];
        #pragma unroll
        for (int j = 0; j < 8; j++) {
            float v = (a[j] - mean) * rstd * garr[j] + barr[j];
            rv[j] = gelu_f(v);
        }
        uint2 hp0, hp1;
        hp0.x = pack_f16x2(rv[0], rv[1]);  hp0.y = pack_f16x2(rv[2], rv[3]);
        hp1.x = pack_f16x2(rv[4], rv[5]);  hp1.y = pack_f16x2(rv[6], rv[7]);
        *reinterpret_cast<uint2*>(Ahi + r * AROW + 4*lane)       = hp0;
        *reinterpret_cast<uint2*>(Ahi + r * AROW + 128 + 4*lane) = hp1;
    }
    __syncthreads();

    // ---- Phase 2: mainloop (fp16 2-term: Ah*Bh + Ah*Bl) ----
    float d[2][4][4];
    #pragma unroll
    for (int mt = 0; mt < 2; mt++)
        #pragma unroll
        for (int nt = 0; nt < 4; nt++)
            #pragma unroll
            for (int q = 0; q < 4; q++) d[mt][nt][q] = 0.f;

    const uint4* Bbase = g_Bfrag + ((size_t)(layer * 32 + wn * 4) * 16) * 32 + lane;

    uint32_t a_hi_addr[2];
    {
        int r = lane & 15;
        int cb = (lane >> 4) * 16;
        #pragma unroll
        for (int mt = 0; mt < 2; mt++) {
            int row = wm * 32 + mt * 16 + r;
            a_hi_addr[mt] = (uint32_t)__cvta_generic_to_shared(Ahi + row * AROW) + cb;
        }
    }

    #pragma unroll 1
    for (int ks = 0; ks < 16; ks++) {
        uint4 bcur[4];
        #pragma unroll
        for (int nt = 0; nt < 4; nt++)
            bcur[nt] = __ldg(&Bbase[(nt * 16 + ks) * 32]);
        const uint32_t koff = ks * 32;
        #pragma unroll
        for (int mt = 0; mt < 2; mt++) {
            uint32_t ah[4];
            ldmx4(ah, a_hi_addr[mt] + koff);
            #pragma unroll
            for (int nt = 0; nt < 4; nt++)
                mma16816(d[mt][nt], ah, bcur[nt].x, bcur[nt].y);
            #pragma unroll
            for (int nt = 0; nt < 4; nt++)
                mma16816(d[mt][nt], ah, bcur[nt].z, bcur[nt].w);
        }
    }

    // ---- stage accum ----
    __syncthreads();
    #pragma unroll
    for (int mt = 0; mt < 2; mt++) {
        int r0 = wm * 32 + mt * 16 + tg;
        #pragma unroll
        for (int nt = 0; nt < 4; nt++) {
            int col = wn * 32 + nt * 8 + tq * 2;
            *reinterpret_cast<float2*>(&stag[r0 * SROW + col]) =
                make_float2(d[mt][nt][0], d[mt][nt][1]);
            *reinterpret_cast<float2*>(&stag[(r0 + 8) * SROW + col]) =
                make_float2(d[mt][nt][2], d[mt][nt][3]);
        }
    }
    __syncthreads();

    // ---- Phase 3: LN2 + gelu + residual -> h_out; 4 rows/warp ----
    #pragma unroll 1
    for (int i = 0; i < 4; i++) {
        int row = wid * 4 + i;
        float4 f0 = *reinterpret_cast<const float4*>(&stag[row * SROW + lane * 8]);
        float4 f1 = *reinterpret_cast<const float4*>(&stag[row * SROW + lane * 8 + 4]);
        float4 bb0 = reinterpret_cast<const float4*>(b11)[lane * 2];
        float4 bb1 = reinterpret_cast<const float4*>(b11)[lane * 2 + 1];
        float v[8] = {f0.x + bb0.x, f0.y + bb0.y, f0.z + bb0.z, f0.w + bb0.w,
                      f1.x + bb1.x, f1.y + bb1.y, f1.z + bb1.z, f1.w + bb1.w};
        float s = 0.f, ss = 0.f;
        #pragma unroll
        for (int j = 0; j < 8; j++) { s += v[j]; ss += v[j] * v[j]; }
        #pragma unroll
        for (int o = 16; o; o >>= 1) {
            s  += __shfl_xor_sync(0xFFFFFFFFu, s,  o);
            ss += __shfl_xor_sync(0xFFFFFFFFu, ss, o);
        }
        float mean = s * (1.0f / F_);
        float rstd = rsqrtf(ss * (1.0f / F_) - mean * mean + 1e-5f);

        float4 gg0 = reinterpret_cast<const float4*>(g2)[lane * 2];
        float4 gg1 = reinterpret_cast<const float4*>(g2)[lane * 2 + 1];
        float4 zb0 = reinterpret_cast<const float4*>(b2)[lane * 2];
        float4 zb1 = reinterpret_cast<const float4*>(b2)[lane * 2 + 1];
        float garr[8] = {gg0.x,gg0.y,gg0.z,gg0.w,gg1.x,gg1.y,gg1.z,gg1.w};
        float barr[8] = {zb0.x,zb0.y,zb0.z,zb0.w,zb1.x,zb1.y,zb1.z,zb1.w};

        float hv[8];
        if (layer == 0) {
            float x0 = __ldg(&x[(size_t)(m0 + row) * 2]);
            float4 w0 = s_wp[lane * 2], w1 = s_wp[lane * 2 + 1];
            float4 p0 = s_bp[lane * 2], p1 = s_bp[lane * 2 + 1];
            hv[0] = x0*w0.x + p0.x; hv[1] = x0*w0.y + p0.y;
            hv[2] = x0*w0.z + p0.z; hv[3] = x0*w0.w + p0.w;
            hv[4] = x0*w1.x + p1.x; hv[5] = x0*w1.y + p1.y;
            hv[6] = x0*w1.z + p1.z; hv[7] = x0*w1.w + p1.w;
        } else {
            const float4* hp = reinterpret_cast<const float4*>(
                h_in + (size_t)(m0 + row) * F_ + lane * 8);
            float4 h0 = hp[0], h1 = hp[1];
            hv[0]=h0.x; hv[1]=h0.y; hv[2]=h0.z; hv[3]=h0.w;
            hv[4]=h1.x; hv[5]=h1.y; hv[6]=h1.z; hv[7]=h1.w;
        }
        #pragma unroll
        for (int j = 0; j < 8; j++) {
            float z = (v[j] - mean) * rstd * garr[j] + barr[j];
            hv[j] += gelu_f(z);
        }
        float4* op = reinterpret_cast<float4*>(
            h_out + (size_t)(m0 + row) * F_ + lane * 8);
        op[0] = make_float4(hv[0], hv[1], hv[2], hv[3]);
        op[1] = make_float4(hv[4], hv[5], hv[6], hv[7]);
    }

    // ---- Phase 4 (layer 2 only): proj mini-GEMM + RQ spline ----
    if (layer == 2) {
        __syncthreads();   // all stag reads/h_out writes done; safe to reuse A

        // rebuild A = h_out * mask (fp16); h_out rows are L2-hot
        {
            int row = tid >> 3;             // 0..63
            int q   = tid & 7;              // 8 float4 per thread
            float mm = __ldg(&mask[m0 + row]);
            const float4* src = reinterpret_cast<const float4*>(
                h_out + (size_t)(m0 + row) * F_) + q * 8;
            #pragma unroll
            for (int j = 0; j < 8; j++) {
                float4 v = src[j];
                v.x *= mm; v.y *= mm; v.z *= mm; v.w *= mm;
                uint2 hp;
                hp.x = pack_f16x2(v.x, v.y);
                hp.y = pack_f16x2(v.z, v.w);
                int c = (q * 8 + j) * 4;
                *reinterpret_cast<uint2*>(Ahi + row * AROW + c) = hp;
            }
        }
        __syncthreads();

        // mini-GEMM: 64x32, 16 warps = 4M x 4N, warp tile 16x8
        {
            const int pwm = wid >> 2;       // 0..3
            const int pwn = wid & 3;        // 0..3
            float pd[4] = {0.f, 0.f, 0.f, 0.f};

            const uint4* PB = g_Pfrag + ((size_t)pwn * 16) * 32 + lane;
            uint32_t pa_hi;
            {
                int r = lane & 15;
                int cb = (lane >> 4) * 16;
                int row = pwm * 16 + r;
                pa_hi = (uint32_t)__cvta_generic_to_shared(Ahi + row * AROW) + cb;
            }
            #pragma unroll 1
            for (int ks = 0; ks < 16; ks++) {
                uint4 bc = __ldg(&PB[ks * 32]);
                const uint32_t koff = ks * 32;
                uint32_t ah[4];
                ldmx4(ah, pa_hi + koff);
                mma16816(pd, ah, bc.x, bc.y);
                mma16816(pd, ah, bc.z, bc.w);
            }
            int r0  = pwm * 16 + tg;
            int col = pwn * 8 + tq * 2;
            *reinterpret_cast<float2*>(&pstag[r0][col])     = make_float2(pd[0], pd[1]);
            *reinterpret_cast<float2*>(&pstag[r0 + 8][col]) = make_float2(pd[2], pd[3]);
        }
        __syncthreads();

        // spline: threads 0..63, one token each
        if (tid < 64) {
            int tok = m0 + tid;
            float m = __ldg(&mask[tok]);

            float proj[PROJ_];
            #pragma unroll
            for (int p = 0; p < PROJ_; p++)
                proj[p] = (pstag[tid][p] + __ldg(&b_proj[p])) * m;

            const float scale = 0.0625f;

            float cw[NB_ + 1], ww[NB_];
            {
                float mx = proj[0] * scale;
                #pragma unroll
                for (int j = 1; j < NB_; j++) mx = fmaxf(mx, proj[j] * scale);
                float e[NB_], sum = 0.f;
                #pragma unroll
                for (int j = 0; j < NB_; j++) { e[j] = expf(proj[j] * scale - mx); sum += e[j]; }
                float inv = 1.0f / sum;
                float cum = 0.f;
                cw[0] = -TBND;
                #pragma unroll
                for (int j = 0; j < NB_; j++) {
                    float wj = 0.001f + (1.0f - 0.001f * NB_) * (e[j] * inv);
                    cum += wj;
                    cw[j + 1] = 2.0f * TBND * cum - TBND;
                }
                cw[NB_] = TBND;
                #pragma unroll
                for (int j = 0; j < NB_; j++) ww[j] = cw[j + 1] - cw[j];
            }
            float ch[NB_ + 1], hh[NB_];
            {
                float mx = proj[NB_] * scale;
                #pragma unroll
                for (int j = 1; j < NB_; j++) mx = fmaxf(mx, proj[NB_ + j] * scale);
                float e[NB_], sum = 0.f;
                #pragma unroll
                for (int j = 0; j < NB_; j++) { e[j] = expf(proj[NB_ + j] * scale - mx); sum += e[j]; }
                float inv = 1.0f / sum;
                float cum = 0.f;
                ch[0] = -TBND;
                #pragma unroll
                for (int j = 0; j < NB_; j++) {
                    float hj = 0.001f + (1.0f - 0.001f * NB_) * (e[j] * inv);
                    cum += hj;
                    ch[j + 1] = 2.0f * TBND * cum - TBND;
                }
                ch[NB_] = TBND;
                #pragma unroll
                for (int j = 0; j < NB_; j++) hh[j] = ch[j + 1] - ch[j];
            }
            float dd[NB_ + 1];
            float cst = logf(expm1f(1.0f - 0.001f));
            dd[0]   = 0.001f + softplus_f(cst);
            dd[NB_] = dd[0];
            #pragma unroll
            for (int k = 1; k < NB_; k++) dd[k] = 0.001f + softplus_f(proj[2 * NB_ + k - 1]);

            float x1 = __ldg(&x[(size_t)tok * 2 + 1]);
            float xc = fminf(fmaxf(x1, -TBND), TBND);
            int idx = 0;
            #pragma unroll
            for (int j = 1; j <= NB_; j++) idx += (xc >= cw[j]) ? 1 : 0;
            if (idx > NB_ - 1) idx = NB_ - 1;

            float icw = cw[idx], ibw = ww[idx];
            float ich = ch[idx], ibh = hh[idx];
            float delta = ibh / ibw;
            float dk = dd[idx], dk1 = dd[idx + 1];
            float th   = (xc - icw) / ibw;
            float th1m = th * (1.0f - th);
            float denom = delta + (dk + dk1 - 2.0f * delta) * th1m;
            float num   = ibh * (delta * th * th + dk * th1m);
            float yv    = ich + num / denom;
            float omth  = 1.0f - th;
            float dnum  = delta * delta * (dk1 * th * th + 2.0f * delta * th1m + dk * omth * omth);
            float lad   = logf(dnum) - 2.0f * logf(denom);

            bool inside = (x1 >= -TBND) && (x1 <= TBND);
            float y1 = inside ? yv : x1;
            lad = inside ? lad : 0.0f;

            out[(size_t)tok * 2]     = __ldg(&x[(size_t)tok * 2]) * m;
            out[(size_t)tok * 2 + 1] = y1 * m;
            g_lad[tok] = lad * m;
        }
    }
}

// ---------------------------------------------------------------------------
// Kernel 5: deterministic per-batch logdet reduction
// ---------------------------------------------------------------------------
__global__ void logdet_kernel(float* __restrict__ out) {
    int b = blockIdx.x, tid = threadIdx.x;
    float s = 0.f;
    for (int j = tid; j < T_; j += 256) s += g_lad[b * T_ + j];
    __shared__ float sh[256];
    sh[tid] = s;
    __syncthreads();
    #pragma unroll
    for (int o = 128; o; o >>= 1) {
        if (tid < o) sh[tid] += sh[tid + o];
        __syncthreads();
    }
    if (tid == 0) out[(size_t)BT_ * 2 + b] = sh[0];
}

// ---------------------------------------------------------------------------
extern "C" void kernel_launch(void* const* d_in, const int* in_sizes, int n_in,
                              void* d_out, int out_size) {
    const float* x      = (const float*)d_in[0];
    const float* mask   = (const float*)d_in[1];
    const float* w_pre  = (const float*)d_in[2];
    const float* b_pre  = (const float*)d_in[3];
    const float* dw_k   = (const float*)d_in[4];
    const float* dw_b   = (const float*)d_in[5];
    const float* w11    = (const float*)d_in[6];
    const float* b11    = (const float*)d_in[7];
    const float* ln1g   = (const float*)d_in[8];
    const float* ln1b   = (const float*)d_in[9];
    const float* ln2g   = (const float*)d_in[10];
    const float* ln2b   = (const float*)d_in[11];
    const float* w_proj = (const float*)d_in[12];
    const float* b_proj = (const float*)d_in[13];
    float* out = (float*)d_out;

    cudaFuncSetAttribute(layer_fused_kernel,
                         cudaFuncAttributeMaxDynamicSharedMemorySize, GSMEM);

    prep_bfrag_kernel<<<NL_ * 32 * 16, 32>>>(w11);
    prep_pfrag_kernel<<<4 * 16, 32>>>(w_proj);

    int dil = 1;
    for (int i = 0; i < NL_; i++) {
        layer_fused_kernel<<<BT_ / 64, 512, GSMEM>>>(
            i, dil, x, mask, w_pre, b_pre,
            dw_k + (size_t)i * KS_ * F_,
            dw_b + (size_t)i * F_,
            ln1g + (size_t)i * F_,
            ln1b + (size_t)i * F_,
            b11 + (size_t)i * F_,
            ln2g + (size_t)i * F_,
            ln2b + (size_t)i * F_,
            b_proj, out);
        dil *= KS_;
    }

    logdet_kernel<<<B_, 256>>>(out);
}